// round 5
// baseline (speedup 1.0000x reference)
#include <cuda_runtime.h>
#include <cstdint>
#include <cstddef>

// ---------------- static problem config ----------------
#define T_STEPS 48
#define HDIM    2048
#define EDIM    512

// ---------------- persistent device state ----------------
__device__ float g_x[EDIM];
__device__ float g_h1[2][HDIM];
__device__ float g_c1[HDIM];
__device__ float g_h2[2][HDIM];
__device__ float g_c2[HDIM];

// ---------------- init ----------------
__global__ void init_kernel() {
    int i = threadIdx.x;
    for (int k = i; k < EDIM; k += blockDim.x) g_x[k] = 0.f;
    for (int k = i; k < HDIM; k += blockDim.x) {
        g_h1[0][k] = 0.f; g_h1[1][k] = 0.f; g_c1[k] = 0.f;
        g_h2[0][k] = 0.f; g_h2[1][k] = 0.f; g_c2[k] = 0.f;
    }
}

__device__ __forceinline__ float sigmoidf_(float v) { return 1.f / (1.f + expf(-v)); }

// ---------------- LSTM cell kernel ----------------
// One block per hidden unit j; block computes the 4 gate dot-products
// (rows j, j+H, j+2H, j+3H of W_ih and W_hh) and does the elementwise update.
// CELL==1: x = g_x (len 512), state = h1/c1. CELL==2: x = new h1 (len 2048), state = h2/c2.
template<int CELL>
__global__ void __launch_bounds__(256) cell_kernel(
    int p,
    const float* __restrict__ W_ih, const float* __restrict__ W_hh,
    const float* __restrict__ b_ih, const float* __restrict__ b_hh)
{
    constexpr int XLEN = (CELL == 1) ? EDIM : HDIM;
    const float* x    = (CELL == 1) ? g_x         : g_h1[p ^ 1];
    const float* h_in = (CELL == 1) ? g_h1[p]     : g_h2[p];
    float* h_out      = (CELL == 1) ? g_h1[p ^ 1] : g_h2[p ^ 1];
    float* c          = (CELL == 1) ? g_c1        : g_c2;

    const int j   = blockIdx.x;       // 0..2047
    const int tid = threadIdx.x;      // 256 threads

    float s0 = 0.f, s1 = 0.f, s2 = 0.f, s3 = 0.f;

    // input part: x (XLEN) vs W_ih rows g*H + j
    {
        const float4* xv = (const float4*)x;
        const float4* w0 = (const float4*)(W_ih + (size_t)(0 * HDIM + j) * XLEN);
        const float4* w1 = (const float4*)(W_ih + (size_t)(1 * HDIM + j) * XLEN);
        const float4* w2 = (const float4*)(W_ih + (size_t)(2 * HDIM + j) * XLEN);
        const float4* w3 = (const float4*)(W_ih + (size_t)(3 * HDIM + j) * XLEN);
        #pragma unroll 2
        for (int k = tid; k < XLEN / 4; k += 256) {
            float4 a = xv[k];
            float4 b0 = w0[k], b1 = w1[k], b2 = w2[k], b3 = w3[k];
            s0 += a.x * b0.x + a.y * b0.y + a.z * b0.z + a.w * b0.w;
            s1 += a.x * b1.x + a.y * b1.y + a.z * b1.z + a.w * b1.w;
            s2 += a.x * b2.x + a.y * b2.y + a.z * b2.z + a.w * b2.w;
            s3 += a.x * b3.x + a.y * b3.y + a.z * b3.z + a.w * b3.w;
        }
    }
    // recurrent part: h_in (HDIM) vs W_hh rows g*H + j
    {
        const float4* hv = (const float4*)h_in;
        const float4* w0 = (const float4*)(W_hh + (size_t)(0 * HDIM + j) * HDIM);
        const float4* w1 = (const float4*)(W_hh + (size_t)(1 * HDIM + j) * HDIM);
        const float4* w2 = (const float4*)(W_hh + (size_t)(2 * HDIM + j) * HDIM);
        const float4* w3 = (const float4*)(W_hh + (size_t)(3 * HDIM + j) * HDIM);
        #pragma unroll 2
        for (int k = tid; k < HDIM / 4; k += 256) {
            float4 a = hv[k];
            float4 b0 = w0[k], b1 = w1[k], b2 = w2[k], b3 = w3[k];
            s0 += a.x * b0.x + a.y * b0.y + a.z * b0.z + a.w * b0.w;
            s1 += a.x * b1.x + a.y * b1.y + a.z * b1.z + a.w * b1.w;
            s2 += a.x * b2.x + a.y * b2.y + a.z * b2.z + a.w * b2.w;
            s3 += a.x * b3.x + a.y * b3.y + a.z * b3.z + a.w * b3.w;
        }
    }

    // block reduction of the 4 partial sums
    #pragma unroll
    for (int o = 16; o; o >>= 1) {
        s0 += __shfl_down_sync(0xffffffffu, s0, o);
        s1 += __shfl_down_sync(0xffffffffu, s1, o);
        s2 += __shfl_down_sync(0xffffffffu, s2, o);
        s3 += __shfl_down_sync(0xffffffffu, s3, o);
    }
    __shared__ float red[4][8];
    const int lane = tid & 31, warp = tid >> 5;
    if (lane == 0) { red[0][warp] = s0; red[1][warp] = s1; red[2][warp] = s2; red[3][warp] = s3; }
    __syncthreads();
    if (tid == 0) {
        float r[4];
        #pragma unroll
        for (int g = 0; g < 4; g++) {
            float a = 0.f;
            #pragma unroll
            for (int w = 0; w < 8; w++) a += red[g][w];
            r[g] = a + b_ih[(size_t)g * HDIM + j] + b_hh[(size_t)g * HDIM + j];
        }
        // gate order i, f, g, o
        float cn = sigmoidf_(r[1]) * c[j] + sigmoidf_(r[0]) * tanhf(r[2]);
        h_out[j] = sigmoidf_(r[3]) * tanhf(cn);
        c[j] = cn;
    }
}

// ---------------- JAX threefry2x32 core (exact bit-replication) ----------------
__device__ __forceinline__ uint32_t rotl32_(uint32_t v, int d) { return (v << d) | (v >> (32 - d)); }

__device__ __forceinline__ void tf2x32(uint32_t k0, uint32_t k1, uint32_t x0, uint32_t x1,
                                       uint32_t& o0, uint32_t& o1)
{
    uint32_t ks0 = k0, ks1 = k1, ks2 = k0 ^ k1 ^ 0x1BD11BDAu;
    x0 += ks0; x1 += ks1;
    const int r0[4] = {13, 15, 26, 6};
    const int r1[4] = {17, 29, 16, 24};
    #pragma unroll
    for (int i = 0; i < 4; i++) { x0 += x1; x1 = rotl32_(x1, r0[i]); x1 ^= x0; }
    x0 += ks1; x1 += ks2 + 1u;
    #pragma unroll
    for (int i = 0; i < 4; i++) { x0 += x1; x1 = rotl32_(x1, r1[i]); x1 ^= x0; }
    x0 += ks2; x1 += ks0 + 2u;
    #pragma unroll
    for (int i = 0; i < 4; i++) { x0 += x1; x1 = rotl32_(x1, r0[i]); x1 ^= x0; }
    x0 += ks0; x1 += ks1 + 3u;
    #pragma unroll
    for (int i = 0; i < 4; i++) { x0 += x1; x1 = rotl32_(x1, r1[i]); x1 ^= x0; }
    x0 += ks1; x1 += ks2 + 4u;
    #pragma unroll
    for (int i = 0; i < 4; i++) { x0 += x1; x1 = rotl32_(x1, r0[i]); x1 ^= x0; }
    x0 += ks2; x1 += ks0 + 5u;
    o0 = x0; o1 = x1;
}

// ---- jax_threefry_partitionable=True (default since JAX 0.4.36) semantics ----
// split(key, 48): keys[t] = (lane0, lane1) of threefry(key, x0=hi(t)=0, x1=lo(t)=t)
__device__ __forceinline__ void step_key(uint32_t t, uint32_t& k0, uint32_t& k1) {
    tf2x32(0u, 1u, 0u, t, k0, k1);   // key(1) = (0, 1)
}
// 32-bit random_bits at flat index j: lane0 XOR lane1 of threefry(key, (0, j))
__device__ __forceinline__ uint32_t rbits32(uint32_t k0, uint32_t k1, uint32_t j) {
    uint32_t a, b;
    tf2x32(k0, k1, 0u, j, a, b);
    return a ^ b;
}

// ---------------- logits + gumbel-max sample + embedding select ----------------
__global__ void __launch_bounds__(256) sample_kernel(
    int t,
    const float* __restrict__ W_out, const float* __restrict__ b_out,
    const float* __restrict__ emb, float* __restrict__ out)
{
    const int p = t & 1;
    const float* h2 = g_h2[p ^ 1];

    __shared__ float logits_s[8];
    __shared__ int   s_row;

    const int tid = threadIdx.x, lane = tid & 31, w = tid >> 5; // 8 warps, one per logit

    {
        const float4* wr = (const float4*)(W_out + ((size_t)t * 8 + w) * HDIM);
        const float4* hv = (const float4*)h2;
        float s = 0.f;
        #pragma unroll 4
        for (int k = lane; k < HDIM / 4; k += 32) {
            float4 a = hv[k], b = wr[k];
            s += a.x * b.x + a.y * b.y + a.z * b.z + a.w * b.w;
        }
        #pragma unroll
        for (int o = 16; o; o >>= 1) s += __shfl_down_sync(0xffffffffu, s, o);
        if (lane == 0) logits_s[w] = s + b_out[t * 8 + w];
    }
    __syncthreads();

    if (tid == 0) {
        const int SIZES[4] = {8, 6, 4, 5};
        const int OFFS[4]  = {0, 8, 14, 18};
        const int type = t & 3;            // t % 4
        const int size = SIZES[type];

        float lg[8];
        #pragma unroll
        for (int i = 0; i < 8; i++) lg[i] = (i < size) ? logits_s[i] : -1e9f;

        // softmax over all 8 (padded entries underflow to 0)
        float m = lg[0];
        #pragma unroll
        for (int i = 1; i < 8; i++) m = fmaxf(m, lg[i]);
        float e[8], sum = 0.f;
        #pragma unroll
        for (int i = 0; i < 8; i++) { e[i] = expf(lg[i] - m); sum += e[i]; }

        // per-step key (partitionable split)
        uint32_t k0, k1;
        step_key((uint32_t)t, k0, k1);

        // gumbel-max (JAX uniform bit construction, first-index tie-break)
        int bi = 0; float best = -3.402823466e38f;
        #pragma unroll
        for (int i = 0; i < 8; i++) {
            uint32_t bits = rbits32(k0, k1, (uint32_t)i);
            float u = __uint_as_float((bits >> 9) | 0x3f800000u) - 1.0f;
            u = fmaxf(u, 1.17549435e-38f);   // minval = float32 tiny
            float gum = -logf(-logf(u));
            float v = lg[i] + gum;
            if (v > best) { best = v; bi = i; }
        }

        out[t]           = (float)bi;        // actions (cast to output dtype)
        out[T_STEPS + t] = e[bi] / sum;      // action_probs
        s_row = OFFS[type] + bi;
    }
    __syncthreads();

    // x_next = emb[offset + ind]
    const int row = s_row;
    const float4* er = (const float4*)(emb + (size_t)row * EDIM);
    float4* xv = (float4*)g_x;
    for (int k = tid; k < EDIM / 4; k += blockDim.x) xv[k] = er[k];
}

// ---------------- launch ----------------
extern "C" void kernel_launch(void* const* d_in, const int* in_sizes, int n_in,
                              void* d_out, int out_size)
{
    const float* emb   = (const float*)d_in[0];
    const float* W_ih1 = (const float*)d_in[1];
    const float* W_hh1 = (const float*)d_in[2];
    const float* b_ih1 = (const float*)d_in[3];
    const float* b_hh1 = (const float*)d_in[4];
    const float* W_ih2 = (const float*)d_in[5];
    const float* W_hh2 = (const float*)d_in[6];
    const float* b_ih2 = (const float*)d_in[7];
    const float* b_hh2 = (const float*)d_in[8];
    const float* W_out = (const float*)d_in[9];
    const float* b_out = (const float*)d_in[10];
    float* out = (float*)d_out;

    init_kernel<<<1, 256>>>();
    for (int t = 0; t < T_STEPS; t++) {
        const int p = t & 1;
        cell_kernel<1><<<HDIM, 256>>>(p, W_ih1, W_hh1, b_ih1, b_hh1);
        cell_kernel<2><<<HDIM, 256>>>(p, W_ih2, W_hh2, b_ih2, b_hh2);
        sample_kernel<<<1, 256>>>(t, W_out, b_out, emb, out);
    }
}

// round 6
// speedup vs baseline: 1.0386x; 1.0386x over previous
#include <cuda_runtime.h>
#include <cstdint>
#include <cstddef>

// ---------------- static problem config ----------------
#define T_STEPS 48
#define HDIM    2048
#define EDIM    512

// ---------------- persistent device state ----------------
__device__ float g_x[EDIM];
__device__ float g_h1[2][HDIM];
__device__ float g_c1[HDIM];
__device__ float g_h2[2][HDIM];
__device__ float g_c2[HDIM];

// ---------------- init ----------------
__global__ void init_kernel() {
    int i = threadIdx.x;
    for (int k = i; k < EDIM; k += blockDim.x) g_x[k] = 0.f;
    for (int k = i; k < HDIM; k += blockDim.x) {
        g_h1[0][k] = 0.f; g_h1[1][k] = 0.f; g_c1[k] = 0.f;
        g_h2[0][k] = 0.f; g_h2[1][k] = 0.f; g_c2[k] = 0.f;
    }
}

__device__ __forceinline__ float sigmoidf_(float v) { return 1.f / (1.f + expf(-v)); }

// ---------------- LSTM cell kernel ----------------
// One block per hidden unit j; block computes the 4 gate dot-products
// (rows j, j+H, j+2H, j+3H of W_ih and W_hh) and does the elementwise update.
// CELL==1: x = g_x (len 512), state = h1/c1. CELL==2: x = new h1 (len 2048), state = h2/c2.
template<int CELL>
__global__ void __launch_bounds__(256) cell_kernel(
    int p,
    const float* __restrict__ W_ih, const float* __restrict__ W_hh,
    const float* __restrict__ b_ih, const float* __restrict__ b_hh)
{
    constexpr int XLEN = (CELL == 1) ? EDIM : HDIM;
    const float* x    = (CELL == 1) ? g_x         : g_h1[p ^ 1];
    const float* h_in = (CELL == 1) ? g_h1[p]     : g_h2[p];
    float* h_out      = (CELL == 1) ? g_h1[p ^ 1] : g_h2[p ^ 1];
    float* c          = (CELL == 1) ? g_c1        : g_c2;

    const int j   = blockIdx.x;       // 0..2047
    const int tid = threadIdx.x;      // 256 threads

    float s0 = 0.f, s1 = 0.f, s2 = 0.f, s3 = 0.f;

    // input part: x (XLEN) vs W_ih rows g*H + j
    {
        const float4* xv = (const float4*)x;
        const float4* w0 = (const float4*)(W_ih + (size_t)(0 * HDIM + j) * XLEN);
        const float4* w1 = (const float4*)(W_ih + (size_t)(1 * HDIM + j) * XLEN);
        const float4* w2 = (const float4*)(W_ih + (size_t)(2 * HDIM + j) * XLEN);
        const float4* w3 = (const float4*)(W_ih + (size_t)(3 * HDIM + j) * XLEN);
        #pragma unroll 2
        for (int k = tid; k < XLEN / 4; k += 256) {
            float4 a = xv[k];
            float4 b0 = w0[k], b1 = w1[k], b2 = w2[k], b3 = w3[k];
            s0 += a.x * b0.x + a.y * b0.y + a.z * b0.z + a.w * b0.w;
            s1 += a.x * b1.x + a.y * b1.y + a.z * b1.z + a.w * b1.w;
            s2 += a.x * b2.x + a.y * b2.y + a.z * b2.z + a.w * b2.w;
            s3 += a.x * b3.x + a.y * b3.y + a.z * b3.z + a.w * b3.w;
        }
    }
    // recurrent part: h_in (HDIM) vs W_hh rows g*H + j
    {
        const float4* hv = (const float4*)h_in;
        const float4* w0 = (const float4*)(W_hh + (size_t)(0 * HDIM + j) * HDIM);
        const float4* w1 = (const float4*)(W_hh + (size_t)(1 * HDIM + j) * HDIM);
        const float4* w2 = (const float4*)(W_hh + (size_t)(2 * HDIM + j) * HDIM);
        const float4* w3 = (const float4*)(W_hh + (size_t)(3 * HDIM + j) * HDIM);
        #pragma unroll 2
        for (int k = tid; k < HDIM / 4; k += 256) {
            float4 a = hv[k];
            float4 b0 = w0[k], b1 = w1[k], b2 = w2[k], b3 = w3[k];
            s0 += a.x * b0.x + a.y * b0.y + a.z * b0.z + a.w * b0.w;
            s1 += a.x * b1.x + a.y * b1.y + a.z * b1.z + a.w * b1.w;
            s2 += a.x * b2.x + a.y * b2.y + a.z * b2.z + a.w * b2.w;
            s3 += a.x * b3.x + a.y * b3.y + a.z * b3.z + a.w * b3.w;
        }
    }

    // block reduction of the 4 partial sums
    #pragma unroll
    for (int o = 16; o; o >>= 1) {
        s0 += __shfl_down_sync(0xffffffffu, s0, o);
        s1 += __shfl_down_sync(0xffffffffu, s1, o);
        s2 += __shfl_down_sync(0xffffffffu, s2, o);
        s3 += __shfl_down_sync(0xffffffffu, s3, o);
    }
    __shared__ float red[4][8];
    const int lane = tid & 31, warp = tid >> 5;
    if (lane == 0) { red[0][warp] = s0; red[1][warp] = s1; red[2][warp] = s2; red[3][warp] = s3; }
    __syncthreads();
    if (tid == 0) {
        float r[4];
        #pragma unroll
        for (int g = 0; g < 4; g++) {
            float a = 0.f;
            #pragma unroll
            for (int w = 0; w < 8; w++) a += red[g][w];
            r[g] = a + b_ih[(size_t)g * HDIM + j] + b_hh[(size_t)g * HDIM + j];
        }
        // gate order i, f, g, o
        float cn = sigmoidf_(r[1]) * c[j] + sigmoidf_(r[0]) * tanhf(r[2]);
        h_out[j] = sigmoidf_(r[3]) * tanhf(cn);
        c[j] = cn;
    }
}

// ---------------- JAX threefry2x32 core (exact bit-replication) ----------------
__device__ __forceinline__ uint32_t rotl32_(uint32_t v, int d) { return (v << d) | (v >> (32 - d)); }

__device__ __forceinline__ void tf2x32(uint32_t k0, uint32_t k1, uint32_t x0, uint32_t x1,
                                       uint32_t& o0, uint32_t& o1)
{
    uint32_t ks0 = k0, ks1 = k1, ks2 = k0 ^ k1 ^ 0x1BD11BDAu;
    x0 += ks0; x1 += ks1;
    const int r0[4] = {13, 15, 26, 6};
    const int r1[4] = {17, 29, 16, 24};
    #pragma unroll
    for (int i = 0; i < 4; i++) { x0 += x1; x1 = rotl32_(x1, r0[i]); x1 ^= x0; }
    x0 += ks1; x1 += ks2 + 1u;
    #pragma unroll
    for (int i = 0; i < 4; i++) { x0 += x1; x1 = rotl32_(x1, r1[i]); x1 ^= x0; }
    x0 += ks2; x1 += ks0 + 2u;
    #pragma unroll
    for (int i = 0; i < 4; i++) { x0 += x1; x1 = rotl32_(x1, r0[i]); x1 ^= x0; }
    x0 += ks0; x1 += ks1 + 3u;
    #pragma unroll
    for (int i = 0; i < 4; i++) { x0 += x1; x1 = rotl32_(x1, r1[i]); x1 ^= x0; }
    x0 += ks1; x1 += ks2 + 4u;
    #pragma unroll
    for (int i = 0; i < 4; i++) { x0 += x1; x1 = rotl32_(x1, r0[i]); x1 ^= x0; }
    x0 += ks2; x1 += ks0 + 5u;
    o0 = x0; o1 = x1;
}

// ---- jax_threefry_partitionable=True (default since JAX 0.4.36) semantics ----
// split(key, 48): keys[t] = (lane0, lane1) of threefry(key, x0=hi(t)=0, x1=lo(t)=t)
__device__ __forceinline__ void step_key(uint32_t t, uint32_t& k0, uint32_t& k1) {
    tf2x32(0u, 1u, 0u, t, k0, k1);   // key(1) = (0, 1)
}
// 32-bit random_bits at flat index j: lane0 XOR lane1 of threefry(key, (0, j))
__device__ __forceinline__ uint32_t rbits32(uint32_t k0, uint32_t k1, uint32_t j) {
    uint32_t a, b;
    tf2x32(k0, k1, 0u, j, a, b);
    return a ^ b;
}

// ---------------- logits + gumbel-max sample + embedding select ----------------
// 1024 threads: 4 warps per logit row (8 rows), max memory-level parallelism on the
// cold 64KB W_out row; then serial finalize + parallel embedding copy.
__global__ void __launch_bounds__(1024) sample_kernel(
    int t,
    const float* __restrict__ W_out, const float* __restrict__ b_out,
    const float* __restrict__ emb, float* __restrict__ out)
{
    const int p = t & 1;
    const float* h2 = g_h2[p ^ 1];

    __shared__ float red[8][4];   // [logit][sub-warp]
    __shared__ int   s_row;

    const int tid   = threadIdx.x;
    const int lane  = tid & 31;
    const int w     = tid >> 5;      // 0..31
    const int logit = w >> 2;        // 0..7
    const int sub   = w & 3;         // 0..3

    {
        const float4* wr = (const float4*)(W_out + ((size_t)t * 8 + logit) * HDIM);
        const float4* hv = (const float4*)h2;
        const int base = sub * 32 + lane;       // 0..127
        // 512 float4 per row / 128 threads = 4 each; fully unrolled -> 4 loads in flight
        float4 b0 = wr[base];
        float4 b1 = wr[base + 128];
        float4 b2 = wr[base + 256];
        float4 b3 = wr[base + 384];
        float4 a0 = hv[base];
        float4 a1 = hv[base + 128];
        float4 a2 = hv[base + 256];
        float4 a3 = hv[base + 384];
        float s = a0.x * b0.x + a0.y * b0.y + a0.z * b0.z + a0.w * b0.w;
        s      += a1.x * b1.x + a1.y * b1.y + a1.z * b1.z + a1.w * b1.w;
        s      += a2.x * b2.x + a2.y * b2.y + a2.z * b2.z + a2.w * b2.w;
        s      += a3.x * b3.x + a3.y * b3.y + a3.z * b3.z + a3.w * b3.w;
        #pragma unroll
        for (int o = 16; o; o >>= 1) s += __shfl_down_sync(0xffffffffu, s, o);
        if (lane == 0) red[logit][sub] = s;
    }
    __syncthreads();

    if (tid == 0) {
        const int SIZES[4] = {8, 6, 4, 5};
        const int OFFS[4]  = {0, 8, 14, 18};
        const int type = t & 3;            // t % 4
        const int size = SIZES[type];

        float lg[8];
        #pragma unroll
        for (int i = 0; i < 8; i++) {
            float s = red[i][0] + red[i][1] + red[i][2] + red[i][3];
            s += b_out[t * 8 + i];
            lg[i] = (i < size) ? s : -1e9f;
        }

        // softmax over all 8 (padded entries underflow to 0)
        float m = lg[0];
        #pragma unroll
        for (int i = 1; i < 8; i++) m = fmaxf(m, lg[i]);
        float e[8], sum = 0.f;
        #pragma unroll
        for (int i = 0; i < 8; i++) { e[i] = expf(lg[i] - m); sum += e[i]; }

        // per-step key (partitionable split)
        uint32_t k0, k1;
        step_key((uint32_t)t, k0, k1);

        // gumbel-max (JAX uniform bit construction, first-index tie-break)
        int bi = 0; float best = -3.402823466e38f;
        #pragma unroll
        for (int i = 0; i < 8; i++) {
            uint32_t bits = rbits32(k0, k1, (uint32_t)i);
            float u = __uint_as_float((bits >> 9) | 0x3f800000u) - 1.0f;
            u = fmaxf(u, 1.17549435e-38f);   // minval = float32 tiny
            float gum = -logf(-logf(u));
            float v = lg[i] + gum;
            if (v > best) { best = v; bi = i; }
        }

        out[t]           = (float)bi;        // actions (cast to output dtype)
        out[T_STEPS + t] = e[bi] / sum;      // action_probs
        s_row = OFFS[type] + bi;
    }
    __syncthreads();

    // x_next = emb[offset + ind]  (128 float4)
    if (tid < 128) {
        const float4* er = (const float4*)(emb + (size_t)s_row * EDIM);
        ((float4*)g_x)[tid] = er[tid];
    }
}

// ---------------- launch ----------------
extern "C" void kernel_launch(void* const* d_in, const int* in_sizes, int n_in,
                              void* d_out, int out_size)
{
    const float* emb   = (const float*)d_in[0];
    const float* W_ih1 = (const float*)d_in[1];
    const float* W_hh1 = (const float*)d_in[2];
    const float* b_ih1 = (const float*)d_in[3];
    const float* b_hh1 = (const float*)d_in[4];
    const float* W_ih2 = (const float*)d_in[5];
    const float* W_hh2 = (const float*)d_in[6];
    const float* b_ih2 = (const float*)d_in[7];
    const float* b_hh2 = (const float*)d_in[8];
    const float* W_out = (const float*)d_in[9];
    const float* b_out = (const float*)d_in[10];
    float* out = (float*)d_out;

    init_kernel<<<1, 256>>>();
    for (int t = 0; t < T_STEPS; t++) {
        const int p = t & 1;
        cell_kernel<1><<<HDIM, 256>>>(p, W_ih1, W_hh1, b_ih1, b_hh1);
        cell_kernel<2><<<HDIM, 256>>>(p, W_ih2, W_hh2, b_ih2, b_hh2);
        sample_kernel<<<1, 1024>>>(t, W_out, b_out, emb, out);
    }
}

// round 7
// speedup vs baseline: 1.4468x; 1.3930x over previous
#include <cuda_runtime.h>
#include <cuda_fp16.h>
#include <cstdint>
#include <cstddef>

// ---------------- static problem config ----------------
#define T_STEPS 48
#define HDIM    2048
#define EDIM    512

// ---------------- persistent device state ----------------
__device__ float g_x[EDIM];
__device__ float g_h1[2][HDIM];
__device__ float g_c1[HDIM];
__device__ float g_h2[2][HDIM];
__device__ float g_c2[HDIM];

// fp16 weight mirrors (static __device__ scratch — allowed; ~109 MB)
__device__ __half g_Wih1[4 * HDIM * EDIM];
__device__ __half g_Whh1[4 * HDIM * HDIM];
__device__ __half g_Wih2[4 * HDIM * HDIM];
__device__ __half g_Whh2[4 * HDIM * HDIM];

// ---------------- init ----------------
__global__ void init_kernel() {
    int i = threadIdx.x;
    for (int k = i; k < EDIM; k += blockDim.x) g_x[k] = 0.f;
    for (int k = i; k < HDIM; k += blockDim.x) {
        g_h1[0][k] = 0.f; g_h1[1][k] = 0.f; g_c1[k] = 0.f;
        g_h2[0][k] = 0.f; g_h2[1][k] = 0.f; g_c2[k] = 0.f;
    }
}

// ---------------- fp32 -> fp16 weight conversion (runs each replay) ----------------
__global__ void __launch_bounds__(256) convert_kernel(const float* __restrict__ src, int which, int n8) {
    __half* dst = (which == 0) ? g_Wih1 : (which == 1) ? g_Whh1 : (which == 2) ? g_Wih2 : g_Whh2;
    int i = blockIdx.x * blockDim.x + threadIdx.x;     // one thread per 8 elements
    if (i < n8) {
        const float4* s = (const float4*)src;
        float4 a = s[2 * i], b = s[2 * i + 1];
        union { __half2 h[4]; uint4 u; } pk;
        pk.h[0] = __floats2half2_rn(a.x, a.y);
        pk.h[1] = __floats2half2_rn(a.z, a.w);
        pk.h[2] = __floats2half2_rn(b.x, b.y);
        pk.h[3] = __floats2half2_rn(b.z, b.w);
        ((uint4*)dst)[i] = pk.u;
    }
}

__device__ __forceinline__ float sigmoidf_(float v) { return 1.f / (1.f + expf(-v)); }

// 8-wide fp16 dot against fp32 activations
__device__ __forceinline__ float dot8(uint4 u, float4 a, float4 b) {
    __half2* h = (__half2*)&u;
    float2 f0 = __half22float2(h[0]);
    float2 f1 = __half22float2(h[1]);
    float2 f2 = __half22float2(h[2]);
    float2 f3 = __half22float2(h[3]);
    return f0.x * a.x + f0.y * a.y + f1.x * a.z + f1.y * a.w
         + f2.x * b.x + f2.y * b.y + f3.x * b.z + f3.y * b.w;
}

// ---------------- LSTM cell kernel (fp16 weights, fp32 accumulate) ----------------
// One block per hidden unit j; 4 gate rows (j, j+H, j+2H, j+3H) of W_ih and W_hh.
template<int CELL>
__global__ void __launch_bounds__(256) cell_kernel(
    int p, const float* __restrict__ b_ih, const float* __restrict__ b_hh)
{
    constexpr int XLEN = (CELL == 1) ? EDIM : HDIM;
    const __half* Wih = (CELL == 1) ? g_Wih1 : g_Wih2;
    const __half* Whh = (CELL == 1) ? g_Whh1 : g_Whh2;
    const float* x    = (CELL == 1) ? g_x         : g_h1[p ^ 1];
    const float* h_in = (CELL == 1) ? g_h1[p]     : g_h2[p];
    float* h_out      = (CELL == 1) ? g_h1[p ^ 1] : g_h2[p ^ 1];
    float* c          = (CELL == 1) ? g_c1        : g_c2;

    const int j   = blockIdx.x;       // 0..2047
    const int tid = threadIdx.x;      // 256 threads

    float s0 = 0.f, s1 = 0.f, s2 = 0.f, s3 = 0.f;

    // input part: x (XLEN) vs W_ih rows g*H + j   (16B load = 8 halves)
    {
        const float4* xv = (const float4*)x;
        const uint4* w0 = (const uint4*)(Wih + (size_t)(0 * HDIM + j) * XLEN);
        const uint4* w1 = (const uint4*)(Wih + (size_t)(1 * HDIM + j) * XLEN);
        const uint4* w2 = (const uint4*)(Wih + (size_t)(2 * HDIM + j) * XLEN);
        const uint4* w3 = (const uint4*)(Wih + (size_t)(3 * HDIM + j) * XLEN);
        for (int k = tid; k < XLEN / 8; k += 256) {
            float4 xa = xv[2 * k], xb = xv[2 * k + 1];
            uint4 u0 = w0[k], u1 = w1[k], u2 = w2[k], u3 = w3[k];
            s0 += dot8(u0, xa, xb);
            s1 += dot8(u1, xa, xb);
            s2 += dot8(u2, xa, xb);
            s3 += dot8(u3, xa, xb);
        }
    }
    // recurrent part: h_in (HDIM) vs W_hh rows g*H + j
    {
        const float4* hv = (const float4*)h_in;
        const uint4* w0 = (const uint4*)(Whh + (size_t)(0 * HDIM + j) * HDIM);
        const uint4* w1 = (const uint4*)(Whh + (size_t)(1 * HDIM + j) * HDIM);
        const uint4* w2 = (const uint4*)(Whh + (size_t)(2 * HDIM + j) * HDIM);
        const uint4* w3 = (const uint4*)(Whh + (size_t)(3 * HDIM + j) * HDIM);
        for (int k = tid; k < HDIM / 8; k += 256) {
            float4 ha = hv[2 * k], hb = hv[2 * k + 1];
            uint4 u0 = w0[k], u1 = w1[k], u2 = w2[k], u3 = w3[k];
            s0 += dot8(u0, ha, hb);
            s1 += dot8(u1, ha, hb);
            s2 += dot8(u2, ha, hb);
            s3 += dot8(u3, ha, hb);
        }
    }

    // block reduction of the 4 partial sums
    #pragma unroll
    for (int o = 16; o; o >>= 1) {
        s0 += __shfl_down_sync(0xffffffffu, s0, o);
        s1 += __shfl_down_sync(0xffffffffu, s1, o);
        s2 += __shfl_down_sync(0xffffffffu, s2, o);
        s3 += __shfl_down_sync(0xffffffffu, s3, o);
    }
    __shared__ float red[4][8];
    const int lane = tid & 31, warp = tid >> 5;
    if (lane == 0) { red[0][warp] = s0; red[1][warp] = s1; red[2][warp] = s2; red[3][warp] = s3; }
    __syncthreads();
    if (tid == 0) {
        float r[4];
        #pragma unroll
        for (int g = 0; g < 4; g++) {
            float a = 0.f;
            #pragma unroll
            for (int w = 0; w < 8; w++) a += red[g][w];
            r[g] = a + b_ih[(size_t)g * HDIM + j] + b_hh[(size_t)g * HDIM + j];
        }
        // gate order i, f, g, o
        float cn = sigmoidf_(r[1]) * c[j] + sigmoidf_(r[0]) * tanhf(r[2]);
        h_out[j] = sigmoidf_(r[3]) * tanhf(cn);
        c[j] = cn;
    }
}

// ---------------- JAX threefry2x32 core (exact bit-replication) ----------------
__device__ __forceinline__ uint32_t rotl32_(uint32_t v, int d) { return (v << d) | (v >> (32 - d)); }

__device__ __forceinline__ void tf2x32(uint32_t k0, uint32_t k1, uint32_t x0, uint32_t x1,
                                       uint32_t& o0, uint32_t& o1)
{
    uint32_t ks0 = k0, ks1 = k1, ks2 = k0 ^ k1 ^ 0x1BD11BDAu;
    x0 += ks0; x1 += ks1;
    const int r0[4] = {13, 15, 26, 6};
    const int r1[4] = {17, 29, 16, 24};
    #pragma unroll
    for (int i = 0; i < 4; i++) { x0 += x1; x1 = rotl32_(x1, r0[i]); x1 ^= x0; }
    x0 += ks1; x1 += ks2 + 1u;
    #pragma unroll
    for (int i = 0; i < 4; i++) { x0 += x1; x1 = rotl32_(x1, r1[i]); x1 ^= x0; }
    x0 += ks2; x1 += ks0 + 2u;
    #pragma unroll
    for (int i = 0; i < 4; i++) { x0 += x1; x1 = rotl32_(x1, r0[i]); x1 ^= x0; }
    x0 += ks0; x1 += ks1 + 3u;
    #pragma unroll
    for (int i = 0; i < 4; i++) { x0 += x1; x1 = rotl32_(x1, r1[i]); x1 ^= x0; }
    x0 += ks1; x1 += ks2 + 4u;
    #pragma unroll
    for (int i = 0; i < 4; i++) { x0 += x1; x1 = rotl32_(x1, r0[i]); x1 ^= x0; }
    x0 += ks2; x1 += ks0 + 5u;
    o0 = x0; o1 = x1;
}

// ---- jax_threefry_partitionable=True semantics ----
__device__ __forceinline__ void step_key(uint32_t t, uint32_t& k0, uint32_t& k1) {
    tf2x32(0u, 1u, 0u, t, k0, k1);   // key(1) = (0, 1)
}
__device__ __forceinline__ uint32_t rbits32(uint32_t k0, uint32_t k1, uint32_t j) {
    uint32_t a, b;
    tf2x32(k0, k1, 0u, j, a, b);
    return a ^ b;
}

// ---------------- logits + gumbel-max sample + embedding select ----------------
__global__ void __launch_bounds__(1024) sample_kernel(
    int t,
    const float* __restrict__ W_out, const float* __restrict__ b_out,
    const float* __restrict__ emb, float* __restrict__ out)
{
    const int p = t & 1;
    const float* h2 = g_h2[p ^ 1];

    __shared__ float red[8][4];   // [logit][sub-warp]
    __shared__ int   s_row;

    const int tid   = threadIdx.x;
    const int lane  = tid & 31;
    const int w     = tid >> 5;      // 0..31
    const int logit = w >> 2;        // 0..7
    const int sub   = w & 3;         // 0..3

    {
        const float4* wr = (const float4*)(W_out + ((size_t)t * 8 + logit) * HDIM);
        const float4* hv = (const float4*)h2;
        const int base = sub * 32 + lane;       // 0..127
        float4 b0 = wr[base];
        float4 b1 = wr[base + 128];
        float4 b2 = wr[base + 256];
        float4 b3 = wr[base + 384];
        float4 a0 = hv[base];
        float4 a1 = hv[base + 128];
        float4 a2 = hv[base + 256];
        float4 a3 = hv[base + 384];
        float s = a0.x * b0.x + a0.y * b0.y + a0.z * b0.z + a0.w * b0.w;
        s      += a1.x * b1.x + a1.y * b1.y + a1.z * b1.z + a1.w * b1.w;
        s      += a2.x * b2.x + a2.y * b2.y + a2.z * b2.z + a2.w * b2.w;
        s      += a3.x * b3.x + a3.y * b3.y + a3.z * b3.z + a3.w * b3.w;
        #pragma unroll
        for (int o = 16; o; o >>= 1) s += __shfl_down_sync(0xffffffffu, s, o);
        if (lane == 0) red[logit][sub] = s;
    }
    __syncthreads();

    if (tid == 0) {
        const int SIZES[4] = {8, 6, 4, 5};
        const int OFFS[4]  = {0, 8, 14, 18};
        const int type = t & 3;
        const int size = SIZES[type];

        float lg[8];
        #pragma unroll
        for (int i = 0; i < 8; i++) {
            float s = red[i][0] + red[i][1] + red[i][2] + red[i][3];
            s += b_out[t * 8 + i];
            lg[i] = (i < size) ? s : -1e9f;
        }

        float m = lg[0];
        #pragma unroll
        for (int i = 1; i < 8; i++) m = fmaxf(m, lg[i]);
        float e[8], sum = 0.f;
        #pragma unroll
        for (int i = 0; i < 8; i++) { e[i] = expf(lg[i] - m); sum += e[i]; }

        uint32_t k0, k1;
        step_key((uint32_t)t, k0, k1);

        int bi = 0; float best = -3.402823466e38f;
        #pragma unroll
        for (int i = 0; i < 8; i++) {
            uint32_t bits = rbits32(k0, k1, (uint32_t)i);
            float u = __uint_as_float((bits >> 9) | 0x3f800000u) - 1.0f;
            u = fmaxf(u, 1.17549435e-38f);
            float gum = -logf(-logf(u));
            float v = lg[i] + gum;
            if (v > best) { best = v; bi = i; }
        }

        out[t]           = (float)bi;
        out[T_STEPS + t] = e[bi] / sum;
        s_row = OFFS[type] + bi;
    }
    __syncthreads();

    if (tid < 128) {
        const float4* er = (const float4*)(emb + (size_t)s_row * EDIM);
        ((float4*)g_x)[tid] = er[tid];
    }
}

// ---------------- launch ----------------
extern "C" void kernel_launch(void* const* d_in, const int* in_sizes, int n_in,
                              void* d_out, int out_size)
{
    const float* emb   = (const float*)d_in[0];
    const float* W_ih1 = (const float*)d_in[1];
    const float* W_hh1 = (const float*)d_in[2];
    const float* b_ih1 = (const float*)d_in[3];
    const float* b_hh1 = (const float*)d_in[4];
    const float* W_ih2 = (const float*)d_in[5];
    const float* W_hh2 = (const float*)d_in[6];
    const float* b_ih2 = (const float*)d_in[7];
    const float* b_hh2 = (const float*)d_in[8];
    const float* W_out = (const float*)d_in[9];
    const float* b_out = (const float*)d_in[10];
    float* out = (float*)d_out;

    // weight conversion (each replay; deterministic)
    {
        const int n8_ih1 = 4 * HDIM * EDIM / 8;   // 524288
        const int n8_hh  = 4 * HDIM * HDIM / 8;   // 2097152
        convert_kernel<<<n8_ih1 / 256, 256>>>(W_ih1, 0, n8_ih1);
        convert_kernel<<<n8_hh  / 256, 256>>>(W_hh1, 1, n8_hh);
        convert_kernel<<<n8_hh  / 256, 256>>>(W_ih2, 2, n8_hh);
        convert_kernel<<<n8_hh  / 256, 256>>>(W_hh2, 3, n8_hh);
    }

    init_kernel<<<1, 256>>>();
    for (int t = 0; t < T_STEPS; t++) {
        const int p = t & 1;
        cell_kernel<1><<<HDIM, 256>>>(p, b_ih1, b_hh1);
        cell_kernel<2><<<HDIM, 256>>>(p, b_ih2, b_hh2);
        sample_kernel<<<1, 1024>>>(t, W_out, b_out, emb, out);
    }
}